// round 5
// baseline (speedup 1.0000x reference)
#include <cuda_runtime.h>
#include <float.h>

#define NB 64
#define NK 5
#define ND 1024
#define NH 32
#define NW 32
#define NHW (NH * NW)

#define GRID1 304                       // 2 CTAs/SM on GB300 (152 SMs)
#define GP 2                            // patches per task
#define NTASK (NB * NHW / GP)           // 32768 tasks
#define TPB 512                         // tasks per batch index (NHW/GP)

// packed per-(b,k) best: (sortable(sim) << 32) | (1023 - n). Zero-init at load;
// gather_kernel re-zeroes after consuming -> deterministic across graph replays.
__device__ unsigned long long g_best[NB * NK];

// ---------------------------------------------------------------------------
// Kernel 1 (persistent, fused sims+argmax):
//   sim[b][k][n] = dot(cue[b][k], patch[b][n]) * rsqrt(||patch||^2)
// (cue normalization is a positive per-k scale -> argmax-invariant, skipped)
// Warp handles 2 patches/task, double-buffered chunk loads, cross-task
// prefetch, per-lane running argmax key, atomicMax flush per batch segment.
// ---------------------------------------------------------------------------
__global__ void __launch_bounds__(256, 4) sims_kernel(const float* __restrict__ cue,
                                                      const float* __restrict__ patches)
{
    const int w    = blockIdx.x;
    const int t0   = (int)(((long long)w * NTASK) / GRID1);
    const int t1   = (int)(((long long)(w + 1) * NTASK) / GRID1);
    const int warp = threadIdx.x >> 5;
    const int lane = threadIdx.x & 31;

    const int b0 = t0 / TPB;                       // range spans at most 2 b values
    __shared__ float s_cue[2 * NK * ND];           // 40 KB

    {
        const int nb = (((t1 - 1) / TPB) != b0) ? 2 : 1;
        const float4* cs4 = (const float4*)(cue + (size_t)b0 * NK * ND);
        float4* sd = (float4*)s_cue;
        for (int i = threadIdx.x; i < nb * (NK * ND / 4); i += 256)
            sd[i] = cs4[i];
    }
    __syncthreads();

    const float4* patches4 = (const float4*)patches;

    int t = t0 + warp;
    if (t >= t1) return;

    size_t base = (size_t)t * (GP * ND / 4);
    float4 v[2][GP];
#pragma unroll
    for (int p = 0; p < GP; p++)
        v[0][p] = patches4[base + (size_t)p * (ND / 4) + lane];

    unsigned long long bestkey = 0;                // lanes 0..9 meaningful
    int curb = t / TPB;

    for (;;) {
        const int bb = t / TPB;

        // flush running best when crossing a batch boundary (at most once)
        if (bb != curb) {
            unsigned long long k2 = __shfl_sync(0xffffffffu, bestkey, lane + 5);
            if (bestkey < k2) bestkey = k2;
            if (lane < NK) atomicMax(&g_best[curb * NK + lane], bestkey);
            bestkey = 0;
            curb = bb;
        }

        const float* cs = s_cue + (bb - b0) * (NK * ND);
        const int tn = t + 8;
        const bool has_next = (tn < t1);
        const size_t nbase = (size_t)tn * (GP * ND / 4);

        float acc[GP][6];
#pragma unroll
        for (int p = 0; p < GP; p++)
#pragma unroll
            for (int j = 0; j < 6; j++) acc[p][j] = 0.f;

#pragma unroll
        for (int u = 0; u < 8; u++) {
            const int cur = u & 1;
            if (u < 7) {
#pragma unroll
                for (int p = 0; p < GP; p++)
                    v[cur ^ 1][p] = patches4[base + (size_t)p * (ND / 4) + (u + 1) * 32 + lane];
            } else if (has_next) {
#pragma unroll
                for (int p = 0; p < GP; p++)
                    v[cur ^ 1][p] = patches4[nbase + (size_t)p * (ND / 4) + lane];
            }
#pragma unroll
            for (int k = 0; k < NK; k++) {
                const float4 c = ((const float4*)(cs + k * ND))[u * 32 + lane];
#pragma unroll
                for (int p = 0; p < GP; p++) {
                    const float4 x = v[cur][p];
                    acc[p][k] += x.x * c.x + x.y * c.y + x.z * c.z + x.w * c.w;
                }
            }
#pragma unroll
            for (int p = 0; p < GP; p++) {
                const float4 x = v[cur][p];
                acc[p][5] += x.x * x.x + x.y * x.y + x.z * x.z + x.w * x.w;
            }
        }

        // butterfly all-reduce (runs under the cross-task prefetch)
#pragma unroll
        for (int p = 0; p < GP; p++)
#pragma unroll
            for (int j = 0; j < 6; j++) {
#pragma unroll
                for (int off = 16; off; off >>= 1)
                    acc[p][j] += __shfl_xor_sync(0xffffffffu, acc[p][j], off);
            }

        // lanes 0..9 fold their (p,k) into the running key
        float outv = 0.f, nrm = 1.f;
#pragma unroll
        for (int p = 0; p < GP; p++)
#pragma unroll
            for (int k = 0; k < NK; k++)
                if (lane == p * NK + k) { outv = acc[p][k]; nrm = acc[p][5]; }

        if (lane < GP * NK) {
            const float sim = outv * rsqrtf(nrm);
            const unsigned int fb = __float_as_uint(sim);
            const unsigned int s  = (fb & 0x80000000u) ? ~fb : (fb | 0x80000000u);
            const int p = lane / NK;
            const int n = (t % TPB) * GP + p;
            const unsigned long long key =
                ((unsigned long long)s << 32) | (unsigned int)(NHW - 1 - n);
            if (key > bestkey) bestkey = key;
        }

        if (!has_next) break;
        t = tn;
        base = nbase;                               // v[0] already holds tn's chunk 0
    }

    // final flush
    {
        unsigned long long k2 = __shfl_sync(0xffffffffu, bestkey, lane + 5);
        if (bestkey < k2) bestkey = k2;
        if (lane < NK) atomicMax(&g_best[curb * NK + lane], bestkey);
    }
}

// ---------------------------------------------------------------------------
// Kernel 2: zero-padded 3x3 neighborhood mean around decoded argmax, then
// reset g_best for the next graph replay.
// ---------------------------------------------------------------------------
__global__ void __launch_bounds__(256) gather_kernel(const float* __restrict__ patches,
                                                     float* __restrict__ out)
{
    const int bk  = blockIdx.x;
    const int b   = bk / NK;
    const int tid = threadIdx.x;

    const unsigned long long key = g_best[bk];
    const int idx = (NHW - 1) - (int)(unsigned int)(key & 0xFFFFFFFFu);
    __syncthreads();
    if (tid == 0) g_best[bk] = 0ull;               // self-clean for next replay

    const int r   = idx >> 5;
    const int cc0 = idx & 31;

    const float4* pb = (const float4*)(patches + (size_t)b * NHW * ND);
    float4 acc = make_float4(0.f, 0.f, 0.f, 0.f);
#pragma unroll
    for (int dy = -1; dy <= 1; dy++) {
        const int rr = r + dy;
        if (rr < 0 || rr >= NH) continue;
#pragma unroll
        for (int dx = -1; dx <= 1; dx++) {
            const int cc = cc0 + dx;
            if (cc < 0 || cc >= NW) continue;
            const float4 q = pb[(size_t)(rr * NW + cc) * (ND / 4) + tid];
            acc.x += q.x; acc.y += q.y; acc.z += q.z; acc.w += q.w;
        }
    }
    const float inv9 = 1.0f / 9.0f;
    acc.x *= inv9; acc.y *= inv9; acc.z *= inv9; acc.w *= inv9;
    ((float4*)out)[(size_t)bk * (ND / 4) + tid] = acc;
}

// ---------------------------------------------------------------------------
extern "C" void kernel_launch(void* const* d_in, const int* in_sizes, int n_in,
                              void* d_out, int out_size)
{
    const float* cue     = (const float*)d_in[0];   // (64,5,1024)
    const float* patches = (const float*)d_in[1];   // (64,32,32,1024)
    float*       out     = (float*)d_out;           // (64,5,1024)

    (void)in_sizes; (void)n_in; (void)out_size;

    sims_kernel<<<GRID1, 256>>>(cue, patches);      // persistent, fused argmax
    gather_kernel<<<NB * NK, 256>>>(patches, out);  // 320 blocks
}

// round 6
// speedup vs baseline: 1.1952x; 1.1952x over previous
#include <cuda_runtime.h>
#include <float.h>

#define NB 64
#define NK 5
#define ND 1024
#define NH 32
#define NW 32
#define NHW 1024

#define GP 4                            // patches per task
#define NTASK (NB * NHW / GP)           // 16384 tasks
#define TPB 256                         // tasks per batch index (NHW/GP)
#define GRID1 152                       // 1 CTA/SM on GB300 (152 SMs)

#define RS 10                           // ring slots per warp
#define DPRE 8                          // prefetch depth in chunks
#define SLOT_BYTES 2048                 // GP patches * 32 lanes * 16B
#define CUE_BYTES (2 * NK * ND * 4)     // 40 KB (block range spans <=2 b)
#define SMEM_TOTAL (CUE_BYTES + 8 * RS * SLOT_BYTES)   // 204800 B

// packed per-(b,k) best: (sortable(sim) << 32) | (1023 - n). Zero at load;
// gather_kernel re-zeroes after consuming -> deterministic across replays.
__device__ unsigned long long g_best[NB * NK];

// ---------------------------------------------------------------------------
__device__ __forceinline__ void cpasync16(unsigned int dst, const float4* src) {
    asm volatile("cp.async.cg.shared.global [%0], [%1], 16;"
                 :: "r"(dst), "l"(src) : "memory");
}
__device__ __forceinline__ void cp_commit() {
    asm volatile("cp.async.commit_group;" ::: "memory");
}
__device__ __forceinline__ void cp_wait7() {
    asm volatile("cp.async.wait_group 7;" ::: "memory");
}
__device__ __forceinline__ void lds_2x64(unsigned long long& a, unsigned long long& b,
                                         unsigned int addr) {
    asm volatile("ld.shared.v2.b64 {%0,%1}, [%2];" : "=l"(a), "=l"(b) : "r"(addr));
}
__device__ __forceinline__ unsigned long long fma2(unsigned long long a,
                                                   unsigned long long b,
                                                   unsigned long long c) {
    unsigned long long d;
    asm("fma.rn.f32x2 %0, %1, %2, %3;" : "=l"(d) : "l"(a), "l"(b), "l"(c));
    return d;
}
__device__ __forceinline__ float unpack_add(unsigned long long v) {
    unsigned int lo, hi;
    asm("mov.b64 {%0,%1}, %2;" : "=r"(lo), "=r"(hi) : "l"(v));
    return __uint_as_float(lo) + __uint_as_float(hi);
}

// ---------------------------------------------------------------------------
// Kernel 1 (persistent, cp.async-pipelined, fused sims+argmax):
//   sim[b][k][n] = dot(cue[b][k], patch[b][n]) * rsqrt(||patch||^2)
// (cue normalization is a positive per-k scale -> argmax-invariant, skipped)
// Per-warp ring of RS chunk slots in smem, DPRE chunks prefetched via
// cp.async; dummy commit_groups at the tail keep wait_group 7 exact.
// ---------------------------------------------------------------------------
__global__ void __launch_bounds__(256, 1) sims_kernel(const float* __restrict__ cue,
                                                      const float* __restrict__ patches)
{
    extern __shared__ char smem[];
    const unsigned int sbase = (unsigned int)__cvta_generic_to_shared(smem);

    const int w    = blockIdx.x;
    const int t0   = (int)(((long long)w * NTASK) / GRID1);
    const int t1   = (int)(((long long)(w + 1) * NTASK) / GRID1);
    const int warp = threadIdx.x >> 5;
    const int lane = threadIdx.x & 31;

    const int b0 = t0 / TPB;                       // range spans <=2 b values
    {
        const int nb = (((t1 - 1) / TPB) != b0) ? 2 : 1;
        const float4* cs4 = (const float4*)(cue + (size_t)b0 * NK * ND);
        float4* sd = (float4*)smem;
        for (int i = threadIdx.x; i < nb * (NK * ND / 4); i += 256)
            sd[i] = cs4[i];
    }
    __syncthreads();

    const float4* patches4 = (const float4*)patches;
    const int tw0 = t0 + warp;
    const int nt  = (tw0 < t1) ? ((t1 - tw0 + 7) >> 3) : 0;
    if (nt == 0) return;
    const int totq = nt * 8;

    const unsigned int ring = sbase + CUE_BYTES + warp * (RS * SLOT_BYTES);

    // ---- prologue: issue DPRE chunk-groups ----
    int qp = 0;
    int sp = 0;                                    // producer slot
#pragma unroll
    for (int i = 0; i < DPRE; i++) {
        if (qp < totq) {
            const int tq = tw0 + ((qp >> 3) << 3); // tw0 + 8*(qp>>3)
            const int u  = qp & 7;
            const size_t gb = (size_t)tq * (GP * ND / 4) + (size_t)u * 32 + lane;
            const unsigned int sdst = ring + sp * SLOT_BYTES + lane * 16;
#pragma unroll
            for (int p = 0; p < GP; p++)
                cpasync16(sdst + p * 512, patches4 + gb + (size_t)p * (ND / 4));
        }
        cp_commit();
        qp++;
        sp = (sp + 1 == RS) ? 0 : sp + 1;
    }

    unsigned long long bestkey = 0;                // lanes 0..19 meaningful
    int curb = tw0 / TPB;
    int sc = 0;                                    // consumer slot

    for (int ti = 0; ti < nt; ti++) {
        const int t  = tw0 + ti * 8;
        const int bb = t / TPB;

        if (bb != curb) {                          // batch-boundary flush
            unsigned long long k2 = __shfl_sync(0xffffffffu, bestkey, lane + 10);
            if (bestkey < k2) bestkey = k2;
            k2 = __shfl_sync(0xffffffffu, bestkey, lane + 5);
            if (bestkey < k2) bestkey = k2;
            if (lane < NK) atomicMax(&g_best[curb * NK + lane], bestkey);
            bestkey = 0;
            curb = bb;
        }

        const unsigned int cbase = sbase + (unsigned int)(bb - b0) * (NK * ND * 4);

        unsigned long long acc2[GP][6];
#pragma unroll
        for (int p = 0; p < GP; p++)
#pragma unroll
            for (int j = 0; j < 6; j++) acc2[p][j] = 0ull;

#pragma unroll
        for (int u = 0; u < 8; u++) {
            // produce chunk qp (or dummy commit at the tail)
            if (qp < totq) {
                const int tq = tw0 + ((qp >> 3) << 3);
                const int uq = qp & 7;
                const size_t gb = (size_t)tq * (GP * ND / 4) + (size_t)uq * 32 + lane;
                const unsigned int sdst = ring + sp * SLOT_BYTES + lane * 16;
#pragma unroll
                for (int p = 0; p < GP; p++)
                    cpasync16(sdst + p * 512, patches4 + gb + (size_t)p * (ND / 4));
            }
            cp_commit();
            qp++;
            sp = (sp + 1 == RS) ? 0 : sp + 1;

            cp_wait7();                            // chunk (qp-1-DPRE) is ready

            // cue chunk u: 5 x (2 packed f32x2)
            unsigned long long cl[NK], ch[NK];
            const unsigned int ca = cbase + (unsigned int)(u * 128 + lane * 4) * 4;
#pragma unroll
            for (int k = 0; k < NK; k++)
                lds_2x64(cl[k], ch[k], ca + (unsigned int)k * (ND * 4));

            const unsigned int sl = ring + sc * SLOT_BYTES + lane * 16;
#pragma unroll
            for (int p = 0; p < GP; p++) {
                unsigned long long xl, xh;
                lds_2x64(xl, xh, sl + p * 512);
#pragma unroll
                for (int k = 0; k < NK; k++)
                    acc2[p][k] = fma2(xl, cl[k], fma2(xh, ch[k], acc2[p][k]));
                acc2[p][5] = fma2(xl, xl, fma2(xh, xh, acc2[p][5]));
            }
            sc = (sc + 1 == RS) ? 0 : sc + 1;
        }

        // fold f32x2 -> f32, butterfly all-reduce
        float acc[GP][6];
#pragma unroll
        for (int p = 0; p < GP; p++)
#pragma unroll
            for (int j = 0; j < 6; j++) {
                float s = unpack_add(acc2[p][j]);
#pragma unroll
                for (int off = 16; off; off >>= 1)
                    s += __shfl_xor_sync(0xffffffffu, s, off);
                acc[p][j] = s;
            }

        float outv = 0.f, nrm = 1.f;
#pragma unroll
        for (int p = 0; p < GP; p++)
#pragma unroll
            for (int k = 0; k < NK; k++)
                if (lane == p * NK + k) { outv = acc[p][k]; nrm = acc[p][5]; }

        if (lane < GP * NK) {
            const float sim = outv * rsqrtf(nrm);
            const unsigned int fb = __float_as_uint(sim);
            const unsigned int s  = (fb & 0x80000000u) ? ~fb : (fb | 0x80000000u);
            const int p = lane / NK;
            const int n = (t % TPB) * GP + p;
            const unsigned long long key =
                ((unsigned long long)s << 32) | (unsigned int)(NHW - 1 - n);
            if (key > bestkey) bestkey = key;
        }
    }

    // final flush
    {
        unsigned long long k2 = __shfl_sync(0xffffffffu, bestkey, lane + 10);
        if (bestkey < k2) bestkey = k2;
        k2 = __shfl_sync(0xffffffffu, bestkey, lane + 5);
        if (bestkey < k2) bestkey = k2;
        if (lane < NK) atomicMax(&g_best[curb * NK + lane], bestkey);
    }
}

// ---------------------------------------------------------------------------
// Kernel 2: zero-padded 3x3 neighborhood mean around decoded argmax.
// 1024 threads/block, one float dim per thread, 9 independent coalesced
// loads -> latency-tolerant. Resets g_best for the next graph replay.
// ---------------------------------------------------------------------------
__global__ void __launch_bounds__(1024) gather_kernel(const float* __restrict__ patches,
                                                      float* __restrict__ out)
{
    const int bk  = blockIdx.x;
    const int b   = bk / NK;
    const int tid = threadIdx.x;

    __shared__ int s_idx;
    if (tid == 0) {
        const unsigned long long key = g_best[bk];
        s_idx = (NHW - 1) - (int)(unsigned int)(key & 0xFFFFFFFFu);
        g_best[bk] = 0ull;                         // self-clean (only tid0 reads)
    }
    __syncthreads();
    const int idx = s_idx;
    const int r   = idx >> 5;
    const int c0  = idx & 31;

    const float* pb = patches + (size_t)b * NHW * ND;
    float acc = 0.f;
#pragma unroll
    for (int dy = -1; dy <= 1; dy++) {
        const int rr = r + dy;
        if (rr < 0 || rr >= NH) continue;
#pragma unroll
        for (int dx = -1; dx <= 1; dx++) {
            const int cc = c0 + dx;
            if (cc < 0 || cc >= NW) continue;
            acc += pb[(size_t)(rr * NW + cc) * ND + tid];
        }
    }
    out[(size_t)bk * ND + tid] = acc * (1.0f / 9.0f);
}

// ---------------------------------------------------------------------------
extern "C" void kernel_launch(void* const* d_in, const int* in_sizes, int n_in,
                              void* d_out, int out_size)
{
    const float* cue     = (const float*)d_in[0];   // (64,5,1024)
    const float* patches = (const float*)d_in[1];   // (64,32,32,1024)
    float*       out     = (float*)d_out;           // (64,5,1024)

    (void)in_sizes; (void)n_in; (void)out_size;

    cudaFuncSetAttribute(sims_kernel,
                         cudaFuncAttributeMaxDynamicSharedMemorySize, SMEM_TOTAL);

    sims_kernel<<<GRID1, 256, SMEM_TOTAL>>>(cue, patches);
    gather_kernel<<<NB * NK, 1024>>>(patches, out);
}

// round 7
// speedup vs baseline: 1.2938x; 1.0825x over previous
#include <cuda_runtime.h>
#include <float.h>

#define NB 64
#define NK 5
#define ND 1024
#define NH 32
#define NW 32
#define NHW 1024

#define GP 4                            // patches per task
#define NTASK (NB * NHW / GP)           // 16384 tasks
#define TPB 256                         // tasks per batch index (NHW/GP)
#define GRID1 152                       // 1 CTA/SM on GB300 (152 SMs)
#define NWARP 16                        // warps per CTA

#define RS 5                            // ring slots per warp
#define DPRE 4                          // prefetch depth in chunks
#define SLOT_BYTES 2048                 // GP patches * 32 lanes * 16B
#define CUE_BYTES (2 * NK * ND * 4)     // 40 KB (block range spans <=2 b)
#define SMEM_TOTAL (CUE_BYTES + NWARP * RS * SLOT_BYTES)   // 204800 B

// packed per-(b,k) best: (sortable(sim) << 32) | (1023 - n). Zero at load;
// gather_kernel re-zeroes after consuming -> deterministic across replays.
__device__ unsigned long long g_best[NB * NK];

// ---------------------------------------------------------------------------
__device__ __forceinline__ void cpasync16(unsigned int dst, const float4* src) {
    asm volatile("cp.async.cg.shared.global [%0], [%1], 16;"
                 :: "r"(dst), "l"(src) : "memory");
}
__device__ __forceinline__ void cp_commit() {
    asm volatile("cp.async.commit_group;" ::: "memory");
}
__device__ __forceinline__ void cp_waitpre() {
    asm volatile("cp.async.wait_group %0;" :: "n"(DPRE - 1) : "memory");
}
__device__ __forceinline__ void lds_2x64(unsigned long long& a, unsigned long long& b,
                                         unsigned int addr) {
    asm volatile("ld.shared.v2.b64 {%0,%1}, [%2];" : "=l"(a), "=l"(b) : "r"(addr));
}
__device__ __forceinline__ unsigned long long fma2(unsigned long long a,
                                                   unsigned long long b,
                                                   unsigned long long c) {
    unsigned long long d;
    asm("fma.rn.f32x2 %0, %1, %2, %3;" : "=l"(d) : "l"(a), "l"(b), "l"(c));
    return d;
}
__device__ __forceinline__ float unpack_add(unsigned long long v) {
    unsigned int lo, hi;
    asm("mov.b64 {%0,%1}, %2;" : "=r"(lo), "=r"(hi) : "l"(v));
    return __uint_as_float(lo) + __uint_as_float(hi);
}

// ---------------------------------------------------------------------------
// Kernel 1 (persistent, cp.async-pipelined, fused sims+argmax):
//   sim[b][k][n] = dot(cue[b][k], patch[b][n]) * rsqrt(||patch||^2)
// (cue normalization is a positive per-k scale -> argmax-invariant, skipped)
// 16 warps/SM; per-warp ring of RS chunk slots, DPRE chunks in flight via
// cp.async; dummy commit_groups at the tail keep wait_group exact.
// ---------------------------------------------------------------------------
__global__ void __launch_bounds__(512, 1) sims_kernel(const float* __restrict__ cue,
                                                      const float* __restrict__ patches)
{
    extern __shared__ char smem[];
    const unsigned int sbase = (unsigned int)__cvta_generic_to_shared(smem);

    const int w    = blockIdx.x;
    const int t0   = (int)(((long long)w * NTASK) / GRID1);
    const int t1   = (int)(((long long)(w + 1) * NTASK) / GRID1);
    const int warp = threadIdx.x >> 5;
    const int lane = threadIdx.x & 31;

    const int b0 = t0 / TPB;                       // range spans <=2 b values
    {
        const int nb = (((t1 - 1) / TPB) != b0) ? 2 : 1;
        const float4* cs4 = (const float4*)(cue + (size_t)b0 * NK * ND);
        float4* sd = (float4*)smem;
        for (int i = threadIdx.x; i < nb * (NK * ND / 4); i += 512)
            sd[i] = cs4[i];
    }
    __syncthreads();

    const float4* patches4 = (const float4*)patches;
    const int tw0 = t0 + warp;
    const int nt  = (tw0 < t1) ? ((t1 - tw0 + NWARP - 1) / NWARP) : 0;
    if (nt == 0) return;
    const int totq = nt * 8;

    const unsigned int ring = sbase + CUE_BYTES + warp * (RS * SLOT_BYTES);

    // ---- prologue: issue DPRE chunk-groups ----
    int qp = 0;
    int sp = 0;                                    // producer slot
#pragma unroll
    for (int i = 0; i < DPRE; i++) {
        if (qp < totq) {
            const int tq = tw0 + (qp >> 3) * NWARP;
            const int u  = qp & 7;
            const size_t gb = (size_t)tq * (GP * ND / 4) + (size_t)u * 32 + lane;
            const unsigned int sdst = ring + sp * SLOT_BYTES + lane * 16;
#pragma unroll
            for (int p = 0; p < GP; p++)
                cpasync16(sdst + p * 512, patches4 + gb + (size_t)p * (ND / 4));
        }
        cp_commit();
        qp++;
        sp = (sp + 1 == RS) ? 0 : sp + 1;
    }

    unsigned long long bestkey = 0;                // lanes 0..19 meaningful
    int curb = tw0 / TPB;
    int sc = 0;                                    // consumer slot

    for (int ti = 0; ti < nt; ti++) {
        const int t  = tw0 + ti * NWARP;
        const int bb = t / TPB;

        if (bb != curb) {                          // batch-boundary flush
            unsigned long long k2 = __shfl_sync(0xffffffffu, bestkey, lane + 10);
            if (bestkey < k2) bestkey = k2;
            k2 = __shfl_sync(0xffffffffu, bestkey, lane + 5);
            if (bestkey < k2) bestkey = k2;
            if (lane < NK) atomicMax(&g_best[curb * NK + lane], bestkey);
            bestkey = 0;
            curb = bb;
        }

        const unsigned int cbase = sbase + (unsigned int)(bb - b0) * (NK * ND * 4);

        unsigned long long acc2[GP][6];
#pragma unroll
        for (int p = 0; p < GP; p++)
#pragma unroll
            for (int j = 0; j < 6; j++) acc2[p][j] = 0ull;

#pragma unroll
        for (int u = 0; u < 8; u++) {
            // produce chunk qp (or dummy commit at the tail)
            if (qp < totq) {
                const int tq = tw0 + (qp >> 3) * NWARP;
                const int uq = qp & 7;
                const size_t gb = (size_t)tq * (GP * ND / 4) + (size_t)uq * 32 + lane;
                const unsigned int sdst = ring + sp * SLOT_BYTES + lane * 16;
#pragma unroll
                for (int p = 0; p < GP; p++)
                    cpasync16(sdst + p * 512, patches4 + gb + (size_t)p * (ND / 4));
            }
            cp_commit();
            qp++;
            sp = (sp + 1 == RS) ? 0 : sp + 1;

            cp_waitpre();                          // chunk (qp-1-DPRE) is ready

            // cue chunk u: 5 x (2 packed f32x2)
            unsigned long long cl[NK], ch[NK];
            const unsigned int ca = cbase + (unsigned int)(u * 128 + lane * 4) * 4;
#pragma unroll
            for (int k = 0; k < NK; k++)
                lds_2x64(cl[k], ch[k], ca + (unsigned int)k * (ND * 4));

            const unsigned int sl = ring + sc * SLOT_BYTES + lane * 16;
#pragma unroll
            for (int p = 0; p < GP; p++) {
                unsigned long long xl, xh;
                lds_2x64(xl, xh, sl + p * 512);
#pragma unroll
                for (int k = 0; k < NK; k++)
                    acc2[p][k] = fma2(xl, cl[k], fma2(xh, ch[k], acc2[p][k]));
                acc2[p][5] = fma2(xl, xl, fma2(xh, xh, acc2[p][5]));
            }
            sc = (sc + 1 == RS) ? 0 : sc + 1;
        }

        // fold f32x2 -> f32, butterfly all-reduce
        float acc[GP][6];
#pragma unroll
        for (int p = 0; p < GP; p++)
#pragma unroll
            for (int j = 0; j < 6; j++) {
                float s = unpack_add(acc2[p][j]);
#pragma unroll
                for (int off = 16; off; off >>= 1)
                    s += __shfl_xor_sync(0xffffffffu, s, off);
                acc[p][j] = s;
            }

        float outv = 0.f, nrm = 1.f;
#pragma unroll
        for (int p = 0; p < GP; p++)
#pragma unroll
            for (int k = 0; k < NK; k++)
                if (lane == p * NK + k) { outv = acc[p][k]; nrm = acc[p][5]; }

        if (lane < GP * NK) {
            const float sim = outv * rsqrtf(nrm);
            const unsigned int fb = __float_as_uint(sim);
            const unsigned int s  = (fb & 0x80000000u) ? ~fb : (fb | 0x80000000u);
            const int p = lane / NK;
            const int n = (t % TPB) * GP + p;
            const unsigned long long key =
                ((unsigned long long)s << 32) | (unsigned int)(NHW - 1 - n);
            if (key > bestkey) bestkey = key;
        }
    }

    // final flush
    {
        unsigned long long k2 = __shfl_sync(0xffffffffu, bestkey, lane + 10);
        if (bestkey < k2) bestkey = k2;
        k2 = __shfl_sync(0xffffffffu, bestkey, lane + 5);
        if (bestkey < k2) bestkey = k2;
        if (lane < NK) atomicMax(&g_best[curb * NK + lane], bestkey);
    }
}

// ---------------------------------------------------------------------------
// Kernel 2: zero-padded 3x3 neighborhood mean around decoded argmax.
// 256 thr/block, float4/thread; all 9 loads unconditional (clamped address,
// 0/1 weight) so they front-batch -> MLP 9. Resets g_best for next replay.
// ---------------------------------------------------------------------------
__global__ void __launch_bounds__(256) gather_kernel(const float* __restrict__ patches,
                                                     float* __restrict__ out)
{
    const int bk  = blockIdx.x;
    const int b   = bk / NK;
    const int tid = threadIdx.x;

    // uniform per-block load (L1 broadcast); every thread reads before the
    // barrier, tid0 resets after it.
    const unsigned long long key = g_best[bk];
    const int idx = (NHW - 1) - (int)(unsigned int)(key & 0xFFFFFFFFu);
    __syncthreads();
    if (tid == 0) g_best[bk] = 0ull;

    const int r  = idx >> 5;
    const int c0 = idx & 31;

    const float4* pb = (const float4*)(patches + (size_t)b * NHW * ND);
    float4 acc = make_float4(0.f, 0.f, 0.f, 0.f);
#pragma unroll
    for (int dy = -1; dy <= 1; dy++) {
#pragma unroll
        for (int dx = -1; dx <= 1; dx++) {
            const int rr = r + dy;
            const int cc = c0 + dx;
            const bool ok = (rr >= 0) & (rr < NH) & (cc >= 0) & (cc < NW);
            const int rrc = min(max(rr, 0), NH - 1);
            const int ccc = min(max(cc, 0), NW - 1);
            const float wgt = ok ? 1.0f : 0.0f;
            const float4 q = pb[(size_t)(rrc * NW + ccc) * (ND / 4) + tid];
            acc.x = fmaf(wgt, q.x, acc.x);
            acc.y = fmaf(wgt, q.y, acc.y);
            acc.z = fmaf(wgt, q.z, acc.z);
            acc.w = fmaf(wgt, q.w, acc.w);
        }
    }
    const float inv9 = 1.0f / 9.0f;
    acc.x *= inv9; acc.y *= inv9; acc.z *= inv9; acc.w *= inv9;
    ((float4*)out)[(size_t)bk * (ND / 4) + tid] = acc;
}

// ---------------------------------------------------------------------------
extern "C" void kernel_launch(void* const* d_in, const int* in_sizes, int n_in,
                              void* d_out, int out_size)
{
    const float* cue     = (const float*)d_in[0];   // (64,5,1024)
    const float* patches = (const float*)d_in[1];   // (64,32,32,1024)
    float*       out     = (float*)d_out;           // (64,5,1024)

    (void)in_sizes; (void)n_in; (void)out_size;

    cudaFuncSetAttribute(sims_kernel,
                         cudaFuncAttributeMaxDynamicSharedMemorySize, SMEM_TOTAL);

    sims_kernel<<<GRID1, 512, SMEM_TOTAL>>>(cue, patches);
    gather_kernel<<<NB * NK, 256>>>(patches, out);
}